// round 1
// baseline (speedup 1.0000x reference)
#include <cuda_runtime.h>
#include <math.h>

#define MAXN 50000
#define MAXE 800000
#define MAXH 4

// ---- scratch (static device allocations; no cudaMalloc anywhere) ----
__device__ float        g_h[MAXN * 100];     // h = x@W for current layer
__device__ float        g_bufA[MAXN * 100];  // layer1 out / layer3 out
__device__ float        g_bufB[MAXN * 50];   // layer2 out
__device__ float        g_el[MAXN * MAXH];
__device__ float        g_er[MAXN * MAXH];
__device__ unsigned int g_menc[MAXN * MAXH];
__device__ float        g_m[MAXN * MAXH];
__device__ float        g_s[MAXN * MAXH];
__device__ float        g_e[MAXE * MAXH];    // e -> ex -> alpha (in place)

// ordered-uint encoding so atomicMax(uint) == max(float)
__device__ __forceinline__ unsigned int fenc(float f) {
    unsigned int u = __float_as_uint(f);
    return (u & 0x80000000u) ? ~u : (u | 0x80000000u);
}
__device__ __forceinline__ float fdec(unsigned int k) {
    unsigned int u = (k & 0x80000000u) ? (k & 0x7FFFFFFFu) : ~k;
    return __uint_as_float(u);
}

// ---------------- SGEMM: H[n,M] = X[n,K] @ W[K,M] ----------------
// 64x64 tile, k-tile 16, 256 threads, 4x4 micro-tile per thread.
__global__ __launch_bounds__(256) void sgemm_kernel(
    const float* __restrict__ X, const float* __restrict__ W,
    float* __restrict__ H, int n, int K, int M)
{
    __shared__ float Xs[16][68];  // [k][row], padded
    __shared__ float Ws[16][68];  // [k][col], padded

    int tx = threadIdx.x & 15;        // col group
    int ty = threadIdx.x >> 4;        // row group
    int row0 = blockIdx.x * 64;
    int col0 = blockIdx.y * 64;

    float acc[4][4] = {};

    for (int k0 = 0; k0 < K; k0 += 16) {
        // load X tile (64 rows x 16 k), transposed into Xs[k][r]
        #pragma unroll
        for (int l = threadIdx.x; l < 64 * 16; l += 256) {
            int r = l >> 4, kk = l & 15;
            int gr = row0 + r, gk = k0 + kk;
            Xs[kk][r] = (gr < n && gk < K) ? X[(long long)gr * K + gk] : 0.f;
        }
        // load W tile (16 k x 64 cols)
        #pragma unroll
        for (int l = threadIdx.x; l < 16 * 64; l += 256) {
            int kk = l >> 6, c = l & 63;
            int gk = k0 + kk, gc = col0 + c;
            Ws[kk][c] = (gk < K && gc < M) ? W[gk * M + gc] : 0.f;
        }
        __syncthreads();

        #pragma unroll
        for (int kk = 0; kk < 16; kk++) {
            float a0 = Xs[kk][ty * 4 + 0];
            float a1 = Xs[kk][ty * 4 + 1];
            float a2 = Xs[kk][ty * 4 + 2];
            float a3 = Xs[kk][ty * 4 + 3];
            float b0 = Ws[kk][tx * 4 + 0];
            float b1 = Ws[kk][tx * 4 + 1];
            float b2 = Ws[kk][tx * 4 + 2];
            float b3 = Ws[kk][tx * 4 + 3];
            acc[0][0] += a0 * b0; acc[0][1] += a0 * b1; acc[0][2] += a0 * b2; acc[0][3] += a0 * b3;
            acc[1][0] += a1 * b0; acc[1][1] += a1 * b1; acc[1][2] += a1 * b2; acc[1][3] += a1 * b3;
            acc[2][0] += a2 * b0; acc[2][1] += a2 * b1; acc[2][2] += a2 * b2; acc[2][3] += a2 * b3;
            acc[3][0] += a3 * b0; acc[3][1] += a3 * b1; acc[3][2] += a3 * b2; acc[3][3] += a3 * b3;
        }
        __syncthreads();
    }

    #pragma unroll
    for (int i = 0; i < 4; i++) {
        int r = row0 + ty * 4 + i;
        if (r >= n) continue;
        #pragma unroll
        for (int j = 0; j < 4; j++) {
            int c = col0 + tx * 4 + j;
            if (c < M) H[(long long)r * M + c] = acc[i][j];
        }
    }
}

// ---------------- el/er + init of m,s ----------------
__global__ __launch_bounds__(256) void eler_init_kernel(
    const float* __restrict__ h, const float* __restrict__ al,
    const float* __restrict__ ar, int n, int H, int D)
{
    int i = blockIdx.x * blockDim.x + threadIdx.x;
    if (i >= n * H) return;
    int node = i / H, hh = i - node * H;
    const float* hp  = h + (long long)node * H * D + hh * D;
    const float* alp = al + hh * D;
    const float* arp = ar + hh * D;
    float l = 0.f, r = 0.f;
    #pragma unroll 5
    for (int d = 0; d < D; d++) { float v = hp[d]; l += v * alp[d]; r += v * arp[d]; }
    g_el[i] = l;
    g_er[i] = r;
    g_menc[i] = 0x007FFFFFu;  // fenc(-inf)
    g_s[i] = 0.f;
}

// ---------------- edge pass 1: e = leaky(el[src]+er[dst]); segment max ----------------
__global__ __launch_bounds__(256) void edge_max_kernel(
    const int* __restrict__ src, const int* __restrict__ dst, int E, int H)
{
    int i = blockIdx.x * blockDim.x + threadIdx.x;
    if (i >= E * H) return;
    int e = i / H, hh = i - e * H;
    int s = src[e], d = dst[e];
    float v = g_el[s * H + hh] + g_er[d * H + hh];
    v = v > 0.f ? v : 0.2f * v;  // leaky_relu, slope 0.2
    g_e[i] = v;
    atomicMax(&g_menc[d * H + hh], fenc(v));
}

// ---------------- decode max, fix non-finite ----------------
__global__ __launch_bounds__(256) void fix_m_kernel(int nH)
{
    int i = blockIdx.x * blockDim.x + threadIdx.x;
    if (i >= nH) return;
    float m = fdec(g_menc[i]);
    if (!isfinite(m)) m = 0.f;
    g_m[i] = m;
}

// ---------------- edge pass 2: ex = exp(e - m[dst]); segment sum ----------------
__global__ __launch_bounds__(256) void edge_exp_kernel(
    const int* __restrict__ dst, int E, int H)
{
    int i = blockIdx.x * blockDim.x + threadIdx.x;
    if (i >= E * H) return;
    int e = i / H, hh = i - e * H;
    int d = dst[e];
    float ex = expf(g_e[i] - g_m[d * H + hh]);
    g_e[i] = ex;
    atomicAdd(&g_s[d * H + hh], ex);
}

// ---------------- edge pass 3: alpha = ex / max(s[dst],1e-9) ----------------
__global__ __launch_bounds__(256) void edge_alpha_kernel(
    const int* __restrict__ dst, int E, int H)
{
    int i = blockIdx.x * blockDim.x + threadIdx.x;
    if (i >= E * H) return;
    int e = i / H, hh = i - e * H;
    int d = dst[e];
    g_e[i] = g_e[i] / fmaxf(g_s[d * H + hh], 1e-9f);
}

// ---------------- init out with bias ----------------
__global__ __launch_bounds__(256) void out_init_kernel(
    float* __restrict__ out, const float* __restrict__ b, int n, int HD)
{
    int i = blockIdx.x * blockDim.x + threadIdx.x;
    if (i >= n * HD) return;
    out[i] = b[i % HD];
}

// ---------------- edge pass 4: out[dst] += alpha * h[src] ----------------
__global__ __launch_bounds__(256) void edge_agg_kernel(
    const int* __restrict__ src, const int* __restrict__ dst,
    const float* __restrict__ hmat, float* __restrict__ out,
    int E, int H, int D)
{
    long long i = (long long)blockIdx.x * blockDim.x + threadIdx.x;
    int HD = H * D;
    if (i >= (long long)E * HD) return;
    int e = (int)(i / HD);
    int f = (int)(i - (long long)e * HD);
    int hh = f / D;
    int s = src[e], d = dst[e];
    float alpha = g_e[e * H + hh];
    atomicAdd(&out[(long long)d * HD + f], alpha * hmat[(long long)s * HD + f]);
}

// ---------------- final FC + sigmoid ----------------
__global__ __launch_bounds__(256) void final_fc_kernel(
    const float* __restrict__ x, const float* __restrict__ fcw,
    const float* __restrict__ fcb, float* __restrict__ out, int n)
{
    int i = blockIdx.x * blockDim.x + threadIdx.x;
    if (i >= n) return;
    float acc = fcb[0];
    #pragma unroll
    for (int j = 0; j < 25; j++) acc += x[i * 25 + j] * fcw[j];
    out[i] = 1.f / (1.f + expf(-acc));
}

// ---------------- host-side layer driver ----------------
static void run_gat_layer(const float* x, const int* src, const int* dst,
                          const float* W, const float* al, const float* ar, const float* b,
                          float* hbuf, float* out,
                          int n, int E, int K, int H, int D)
{
    int M = H * D;
    dim3 gemm_grid((n + 63) / 64, (M + 63) / 64);
    sgemm_kernel<<<gemm_grid, 256>>>(x, W, hbuf, n, K, M);

    int nH = n * H;
    eler_init_kernel<<<(nH + 255) / 256, 256>>>(hbuf, al, ar, n, H, D);

    int EH = E * H;
    edge_max_kernel<<<(EH + 255) / 256, 256>>>(src, dst, E, H);
    fix_m_kernel<<<(nH + 255) / 256, 256>>>(nH);
    edge_exp_kernel<<<(EH + 255) / 256, 256>>>(dst, E, H);
    edge_alpha_kernel<<<(EH + 255) / 256, 256>>>(dst, E, H);

    int nHD = n * M;
    out_init_kernel<<<(nHD + 255) / 256, 256>>>(out, b, n, M);

    long long total = (long long)E * M;
    int blocks = (int)((total + 255) / 256);
    edge_agg_kernel<<<blocks, 256>>>(src, dst, hbuf, out, E, H, D);
}

extern "C" void kernel_launch(void* const* d_in, const int* in_sizes, int n_in,
                              void* d_out, int out_size)
{
    const float* features = (const float*)d_in[0];
    const int*   src      = (const int*)d_in[1];
    const int*   dst      = (const int*)d_in[2];
    const float* W1  = (const float*)d_in[3];
    const float* al1 = (const float*)d_in[4];
    const float* ar1 = (const float*)d_in[5];
    const float* b1  = (const float*)d_in[6];
    const float* W2  = (const float*)d_in[7];
    const float* al2 = (const float*)d_in[8];
    const float* ar2 = (const float*)d_in[9];
    const float* b2  = (const float*)d_in[10];
    const float* W3  = (const float*)d_in[11];
    const float* al3 = (const float*)d_in[12];
    const float* ar3 = (const float*)d_in[13];
    const float* b3  = (const float*)d_in[14];
    const float* fcw = (const float*)d_in[15];
    const float* fcb = (const float*)d_in[16];

    int n = in_sizes[0] / 93;
    int E = in_sizes[1];

    float *h_p, *A_p, *B_p;
    cudaGetSymbolAddress((void**)&h_p, g_h);
    cudaGetSymbolAddress((void**)&A_p, g_bufA);
    cudaGetSymbolAddress((void**)&B_p, g_bufB);

    // layer 1: 93 -> 4 heads x 25
    run_gat_layer(features, src, dst, W1, al1, ar1, b1, h_p, A_p, n, E, 93, 4, 25);
    // layer 2: 100 -> 2 heads x 25
    run_gat_layer(A_p, src, dst, W2, al2, ar2, b2, h_p, B_p, n, E, 100, 2, 25);
    // layer 3: 50 -> 1 head x 25
    run_gat_layer(B_p, src, dst, W3, al3, ar3, b3, h_p, A_p, n, E, 50, 1, 25);

    // final: sigmoid(h @ fc_w + fc_b)
    final_fc_kernel<<<(n + 255) / 256, 256>>>(A_p, fcw, fcb, (float*)d_out, n);
}

// round 17
// speedup vs baseline: 1.6040x; 1.6040x over previous
#include <cuda_runtime.h>
#include <math.h>

#define MAXN 50000
#define MAXE 800000
#define MAXH 4

// ---- static device scratch (no cudaMalloc anywhere) ----
__device__ float g_h[MAXN * 100];      // h = x@W for current layer
__device__ float g_bufA[MAXN * 100];   // layer outputs ping
__device__ float g_bufB[MAXN * 50];    // layer outputs pong
__device__ float g_el[MAXN * MAXH];
__device__ float g_er[MAXN * MAXH];
__device__ float g_scr[MAXE * MAXH];   // per-edge scratch (leaky value v), CSR order
__device__ int   g_srcidx[MAXE];       // CSR: src node per incoming edge
__device__ int   g_rowptr[MAXN + 1];
__device__ int   g_cnt[MAXN];
__device__ int   g_fill[MAXN];

// ================= CSR construction =================
__global__ __launch_bounds__(256) void zero_cnt_kernel(int n) {
    int i = blockIdx.x * blockDim.x + threadIdx.x;
    if (i < n) g_cnt[i] = 0;
}

__global__ __launch_bounds__(256) void count_kernel(const int* __restrict__ dst, int E) {
    int i = blockIdx.x * blockDim.x + threadIdx.x;
    if (i < E) atomicAdd(&g_cnt[dst[i]], 1);
}

// single-block exclusive scan over g_cnt -> g_rowptr (and copy to g_fill)
__global__ __launch_bounds__(1024) void scan_kernel(int n) {
    __shared__ int sdata[1024];
    __shared__ int running;
    if (threadIdx.x == 0) running = 0;
    __syncthreads();
    for (int base = 0; base < n; base += 1024) {
        int i = base + threadIdx.x;
        int v = (i < n) ? g_cnt[i] : 0;
        sdata[threadIdx.x] = v;
        __syncthreads();
        #pragma unroll
        for (int off = 1; off < 1024; off <<= 1) {
            int t = (threadIdx.x >= off) ? sdata[threadIdx.x - off] : 0;
            __syncthreads();
            sdata[threadIdx.x] += t;
            __syncthreads();
        }
        int excl = sdata[threadIdx.x] - v + running;
        if (i < n) { g_rowptr[i] = excl; g_fill[i] = excl; }
        __syncthreads();
        if (threadIdx.x == 0) running += sdata[1023];
        __syncthreads();
    }
    if (threadIdx.x == 0) g_rowptr[n] = running;
}

__global__ __launch_bounds__(256) void scatter_kernel(
    const int* __restrict__ src, const int* __restrict__ dst, int E) {
    int i = blockIdx.x * blockDim.x + threadIdx.x;
    if (i >= E) return;
    int pos = atomicAdd(&g_fill[dst[i]], 1);
    g_srcidx[pos] = src[i];
}

// ================= SGEMM: H[n,M] = X[n,K] @ W[K,M] =================
__global__ __launch_bounds__(256) void sgemm_kernel(
    const float* __restrict__ X, const float* __restrict__ W,
    float* __restrict__ Hout, int n, int K, int M)
{
    __shared__ float Xs[16][68];
    __shared__ float Ws[16][68];

    int tx = threadIdx.x & 15;
    int ty = threadIdx.x >> 4;
    int row0 = blockIdx.x * 64;
    int col0 = blockIdx.y * 64;

    float acc[4][4] = {};

    for (int k0 = 0; k0 < K; k0 += 16) {
        for (int l = threadIdx.x; l < 64 * 16; l += 256) {
            int r = l >> 4, kk = l & 15;
            int gr = row0 + r, gk = k0 + kk;
            Xs[kk][r] = (gr < n && gk < K) ? X[(long long)gr * K + gk] : 0.f;
        }
        for (int l = threadIdx.x; l < 16 * 64; l += 256) {
            int kk = l >> 6, c = l & 63;
            int gk = k0 + kk, gc = col0 + c;
            Ws[kk][c] = (gk < K && gc < M) ? W[gk * M + gc] : 0.f;
        }
        __syncthreads();
        #pragma unroll
        for (int kk = 0; kk < 16; kk++) {
            float a0 = Xs[kk][ty * 4 + 0], a1 = Xs[kk][ty * 4 + 1];
            float a2 = Xs[kk][ty * 4 + 2], a3 = Xs[kk][ty * 4 + 3];
            float b0 = Ws[kk][tx * 4 + 0], b1 = Ws[kk][tx * 4 + 1];
            float b2 = Ws[kk][tx * 4 + 2], b3 = Ws[kk][tx * 4 + 3];
            acc[0][0] += a0 * b0; acc[0][1] += a0 * b1; acc[0][2] += a0 * b2; acc[0][3] += a0 * b3;
            acc[1][0] += a1 * b0; acc[1][1] += a1 * b1; acc[1][2] += a1 * b2; acc[1][3] += a1 * b3;
            acc[2][0] += a2 * b0; acc[2][1] += a2 * b1; acc[2][2] += a2 * b2; acc[2][3] += a2 * b3;
            acc[3][0] += a3 * b0; acc[3][1] += a3 * b1; acc[3][2] += a3 * b2; acc[3][3] += a3 * b3;
        }
        __syncthreads();
    }

    #pragma unroll
    for (int i = 0; i < 4; i++) {
        int r = row0 + ty * 4 + i;
        if (r >= n) continue;
        #pragma unroll
        for (int j = 0; j < 4; j++) {
            int c = col0 + tx * 4 + j;
            if (c < M) Hout[(long long)r * M + c] = acc[i][j];
        }
    }
}

// ================= el/er per (node,head) =================
__global__ __launch_bounds__(256) void eler_kernel(
    const float* __restrict__ h, const float* __restrict__ al,
    const float* __restrict__ ar, int n, int H, int D)
{
    int i = blockIdx.x * blockDim.x + threadIdx.x;
    if (i >= n * H) return;
    int node = i / H, hh = i - node * H;
    const float* hp  = h + (long long)node * H * D + hh * D;
    const float* alp = al + hh * D;
    const float* arp = ar + hh * D;
    float l = 0.f, r = 0.f;
    #pragma unroll 5
    for (int d = 0; d < D; d++) { float v = hp[d]; l += v * alp[d]; r += v * arp[d]; }
    g_el[i] = l;
    g_er[i] = r;
}

// ================= fused softmax + aggregation: warp per (node,head) =================
// pass 1 (edge-parallel, online softmax): v = leaky(el[src]+er[dst]); store v;
//   per-lane running (m, s); combine across warp via shuffles.
// pass 2 (feature-parallel, 2-wide pipelined): acc = sum_j exp(v_j - m) * h[src_j, lane];
//   out = acc/s + b.
// FUSE_FC=1 (H==1): d_out[node] = sigmoid(dot(out_row, fcw) + fcb)
template <int FUSE_FC>
__global__ __launch_bounds__(256) void gat_node_kernel(
    const float* __restrict__ h, const float* __restrict__ b,
    float* __restrict__ out,
    const float* __restrict__ fcw, const float* __restrict__ fcb,
    int n, int H, int D, int E)
{
    int warp_in_blk = threadIdx.x >> 5;
    int lane = threadIdx.x & 31;
    int w = blockIdx.x * (blockDim.x >> 5) + warp_in_blk;
    if (w >= n * H) return;
    int node = w / H;
    int hh   = w - node * H;

    int rs = g_rowptr[node];
    int re = g_rowptr[node + 1];
    float er_d = g_er[node * H + hh];
    size_t scrbase = (size_t)hh * E;

    // ---- pass 1: compute v, store, per-lane online (m, s) ----
    float lm = -INFINITY;   // lane max
    float ls = 0.f;         // lane sum of exp(v - lm)
    for (int j = rs + lane; j < re; j += 32) {
        int s = g_srcidx[j];
        float v = g_el[s * H + hh] + er_d;
        v = v > 0.f ? v : 0.2f * v;
        g_scr[scrbase + j] = v;
        if (v > lm) {
            ls = ls * __expf(lm - v) + 1.f;   // rescale old sum; exp(v-v)=1
            lm = v;
        } else {
            ls += __expf(v - lm);
        }
    }
    // combine across warp: global max, then rescale lane sums
    float m = lm;
    #pragma unroll
    for (int o = 16; o; o >>= 1) m = fmaxf(m, __shfl_xor_sync(0xffffffffu, m, o));
    float ssum = (ls > 0.f) ? ls * __expf(lm - m) : 0.f;
    #pragma unroll
    for (int o = 16; o; o >>= 1) ssum += __shfl_xor_sync(0xffffffffu, ssum, o);
    float rinv = 1.f / fmaxf(ssum, 1e-9f);

    // ---- pass 2: feature-parallel aggregation, 2-wide software pipeline ----
    int HD = H * D;
    const float* hbase = h + hh * D;
    bool active = (lane < D);
    float acc0 = 0.f, acc1 = 0.f;
    int j = rs;
    for (; j + 2 <= re; j += 2) {
        // issue both edges' broadcast metadata, then both gathers -> MLP 2
        int   s0 = g_srcidx[j];
        int   s1 = g_srcidx[j + 1];
        float v0 = g_scr[scrbase + j];
        float v1 = g_scr[scrbase + j + 1];
        float h0 = active ? hbase[(size_t)s0 * HD + lane] : 0.f;
        float h1 = active ? hbase[(size_t)s1 * HD + lane] : 0.f;
        acc0 += __expf(v0 - m) * h0;
        acc1 += __expf(v1 - m) * h1;
    }
    if (j < re) {
        int   s0 = g_srcidx[j];
        float v0 = g_scr[scrbase + j];
        float h0 = active ? hbase[(size_t)s0 * HD + lane] : 0.f;
        acc0 += __expf(v0 - m) * h0;
    }
    float acc = (acc0 + acc1) * rinv;

    if (FUSE_FC) {
        float val = active ? (acc + b[lane]) : 0.f;
        float p = active ? val * fcw[lane] : 0.f;
        #pragma unroll
        for (int o = 16; o; o >>= 1) p += __shfl_xor_sync(0xffffffffu, p, o);
        if (lane == 0) out[node] = 1.f / (1.f + __expf(-(p + fcb[0])));
    } else {
        if (active)
            out[(size_t)node * HD + hh * D + lane] = acc + b[hh * D + lane];
    }
}

// ================= host driver =================
static void run_gat_layer(const float* x, const float* W, const float* al,
                          const float* ar, const float* b,
                          float* hbuf, float* out,
                          int n, int E, int K, int H, int D,
                          const float* fcw, const float* fcb, float* final_out)
{
    int M = H * D;
    dim3 gemm_grid((n + 63) / 64, (M + 63) / 64);
    sgemm_kernel<<<gemm_grid, 256>>>(x, W, hbuf, n, K, M);

    int nH = n * H;
    eler_kernel<<<(nH + 255) / 256, 256>>>(hbuf, al, ar, n, H, D);

    int blocks = (nH + 7) / 8;
    if (fcw) {
        gat_node_kernel<1><<<blocks, 256>>>(hbuf, b, final_out, fcw, fcb, n, H, D, E);
    } else {
        gat_node_kernel<0><<<blocks, 256>>>(hbuf, b, out, nullptr, nullptr, n, H, D, E);
    }
}

extern "C" void kernel_launch(void* const* d_in, const int* in_sizes, int n_in,
                              void* d_out, int out_size)
{
    const float* features = (const float*)d_in[0];
    const int*   src      = (const int*)d_in[1];
    const int*   dst      = (const int*)d_in[2];
    const float* W1  = (const float*)d_in[3];
    const float* al1 = (const float*)d_in[4];
    const float* ar1 = (const float*)d_in[5];
    const float* b1  = (const float*)d_in[6];
    const float* W2  = (const float*)d_in[7];
    const float* al2 = (const float*)d_in[8];
    const float* ar2 = (const float*)d_in[9];
    const float* b2  = (const float*)d_in[10];
    const float* W3  = (const float*)d_in[11];
    const float* al3 = (const float*)d_in[12];
    const float* ar3 = (const float*)d_in[13];
    const float* b3  = (const float*)d_in[14];
    const float* fcw = (const float*)d_in[15];
    const float* fcb = (const float*)d_in[16];

    int n = in_sizes[0] / 93;
    int E = in_sizes[1];

    float *h_p, *A_p, *B_p;
    cudaGetSymbolAddress((void**)&h_p, g_h);
    cudaGetSymbolAddress((void**)&A_p, g_bufA);
    cudaGetSymbolAddress((void**)&B_p, g_bufB);

    // ---- build CSR (incoming edges per node) ----
    zero_cnt_kernel<<<(n + 255) / 256, 256>>>(n);
    count_kernel<<<(E + 255) / 256, 256>>>(dst, E);
    scan_kernel<<<1, 1024>>>(n);
    scatter_kernel<<<(E + 255) / 256, 256>>>(src, dst, E);

    // ---- 3 GAT layers ----
    run_gat_layer(features, W1, al1, ar1, b1, h_p, A_p, n, E, 93, 4, 25,
                  nullptr, nullptr, nullptr);
    run_gat_layer(A_p, W2, al2, ar2, b2, h_p, B_p, n, E, 100, 2, 25,
                  nullptr, nullptr, nullptr);
    // layer 3 fuses final FC + sigmoid into its epilogue
    run_gat_layer(B_p, W3, al3, ar3, b3, h_p, nullptr, n, E, 50, 1, 25,
                  fcw, fcb, (float*)d_out);
}